// round 6
// baseline (speedup 1.0000x reference)
#include <cuda_runtime.h>
#include <math.h>
#include <stdint.h>

#define NN 100000
#define NE 1600000
#define HD 128
#define EPSV 1e-5f

// ---------------- scratch (static device globals; no allocation) ----------------
__device__ int   g_deg[NN];
__device__ int   g_fill[NN];
__device__ int   g_off[NN + 1];
__device__ float g_dinv[NN];
__device__ int   g_csrc[NE];
__device__ float g_bufA[(size_t)NN * HD];
__device__ float g_bufB[(size_t)NN * HD];
__device__ float g_Wc[HD * 2];
__device__ float g_bc[2];

// ---------------- graph preprocessing ----------------
__global__ void k_zero() {
    int i = blockIdx.x * blockDim.x + threadIdx.x;
    if (i < NN) { g_deg[i] = 0; g_fill[i] = 0; }
}

__global__ void k_count(const int* __restrict__ dst) {
    int i = blockIdx.x * blockDim.x + threadIdx.x;
    if (i < NE) atomicAdd(&g_deg[dst[i]], 1);
}

// single-block exclusive scan of g_deg -> g_off ; also dinv = rsqrt(deg+1)
__global__ void k_scan() {
    __shared__ int ss[1024];
    const int T = 1024;
    const int CH = (NN + T - 1) / T;
    int t = threadIdx.x;
    int lo = t * CH; if (lo > NN) lo = NN;
    int hi = lo + CH; if (hi > NN) hi = NN;
    int s = 0;
    for (int i = lo; i < hi; i++) s += g_deg[i];
    ss[t] = s;
    __syncthreads();
    for (int d = 1; d < T; d <<= 1) {
        int v = (t >= d) ? ss[t - d] : 0;
        __syncthreads();
        ss[t] += v;
        __syncthreads();
    }
    int run = (t == 0) ? 0 : ss[t - 1];
    for (int i = lo; i < hi; i++) {
        g_off[i] = run;
        int dg = g_deg[i];
        run += dg;
        g_dinv[i] = rsqrtf((float)(dg + 1));   // +1 self loop
    }
    if (t == T - 1) g_off[NN] = run;
}

__global__ void k_scatter(const int* __restrict__ src, const int* __restrict__ dst) {
    int i = blockIdx.x * blockDim.x + threadIdx.x;
    if (i < NE) {
        int d = dst[i];
        int p = g_off[d] + atomicAdd(&g_fill[d], 1);
        g_csrc[p] = src[i];
    }
}

// ---------------- tensor-core TF32 GEMM (3xTF32): C[M,128] = A[M,128]@B[128,128] ----
__device__ __forceinline__ uint32_t f2tf(float f) {
    uint32_t u;
    asm("cvt.rna.tf32.f32 %0, %1;" : "=r"(u) : "f"(f));
    return u;
}
__device__ __forceinline__ void mma_tf32(float* d, const uint32_t* a, uint32_t b0, uint32_t b1) {
    asm volatile(
        "mma.sync.aligned.m16n8k8.row.col.f32.tf32.tf32.f32 "
        "{%0,%1,%2,%3}, {%4,%5,%6,%7}, {%8,%9}, {%0,%1,%2,%3};"
        : "+f"(d[0]), "+f"(d[1]), "+f"(d[2]), "+f"(d[3])
        : "r"(a[0]), "r"(a[1]), "r"(a[2]), "r"(a[3]), "r"(b0), "r"(b1));
}

// block: 256 thr (8 warps), 128 rows x full 128 cols, K=128 in one pass.
// smem: A frags [8 gm][16 k][32 lane] float4 (64KB) + B frags [16 t][16 k][32 lane] float2 (64KB)
__global__ __launch_bounds__(256) void gemm_tc(const float* __restrict__ A,
                                               const float* __restrict__ B,
                                               float* __restrict__ C, int M) {
    extern __shared__ float sm[];
    float4* aF = (float4*)sm;                       // 8*16*32 float4 = 64 KB
    float2* bF = (float2*)(sm + 8 * 16 * 32 * 4);   // 16*16*32 float2 = 64 KB
    int tid = threadIdx.x;
    int bm = blockIdx.x * 128;

    // stage B fragments (weights, 128x128), mma row.col: B k-major per column
    for (int s = tid; s < 16 * 16 * 32; s += 256) {
        int t  = s >> 9;          // n-tile
        int k  = (s >> 5) & 15;   // k-step
        int ln = s & 31;
        int g = ln >> 2, tt = ln & 3;
        int r0 = k * 8 + tt, c = t * 8 + g;
        bF[s] = make_float2(B[r0 * 128 + c], B[(r0 + 4) * 128 + c]);
    }
    // stage A fragments (this block's 128 rows)
    for (int s = tid; s < 8 * 16 * 32; s += 256) {
        int gm = s >> 9;
        int k  = (s >> 5) & 15;
        int ln = s & 31;
        int g = ln >> 2, tt = ln & 3;
        int r0 = bm + gm * 16 + g;
        int r1 = r0 + 8;
        int c0 = k * 8 + tt, c1 = c0 + 4;
        float4 v;
        v.x = (r0 < M) ? A[(size_t)r0 * 128 + c0] : 0.f;
        v.y = (r1 < M) ? A[(size_t)r1 * 128 + c0] : 0.f;
        v.z = (r0 < M) ? A[(size_t)r0 * 128 + c1] : 0.f;
        v.w = (r1 < M) ? A[(size_t)r1 * 128 + c1] : 0.f;
        aF[s] = v;
    }
    __syncthreads();

    int wid = tid >> 5, ln = tid & 31;
    int wm = wid & 3;    // m-group: m-tiles wm*2, wm*2+1
    int wn = wid >> 2;   // n-half: n-tiles wn*8 .. +7

    float acc[2][8][4] = {};

#pragma unroll
    for (int k = 0; k < 16; k++) {
        uint32_t ah[2][4], al[2][4];
#pragma unroll
        for (int mi = 0; mi < 2; mi++) {
            float4 a = aF[((wm * 2 + mi) * 16 + k) * 32 + ln];
            ah[mi][0] = f2tf(a.x); al[mi][0] = f2tf(a.x - __uint_as_float(ah[mi][0]));
            ah[mi][1] = f2tf(a.y); al[mi][1] = f2tf(a.y - __uint_as_float(ah[mi][1]));
            ah[mi][2] = f2tf(a.z); al[mi][2] = f2tf(a.z - __uint_as_float(ah[mi][2]));
            ah[mi][3] = f2tf(a.w); al[mi][3] = f2tf(a.w - __uint_as_float(ah[mi][3]));
        }
#pragma unroll
        for (int ti = 0; ti < 8; ti++) {
            float2 b = bF[((wn * 8 + ti) * 16 + k) * 32 + ln];
            uint32_t bh0 = f2tf(b.x), bl0 = f2tf(b.x - __uint_as_float(bh0));
            uint32_t bh1 = f2tf(b.y), bl1 = f2tf(b.y - __uint_as_float(bh1));
#pragma unroll
            for (int mi = 0; mi < 2; mi++) {
                mma_tf32(acc[mi][ti], ah[mi], bh0, bh1);
                mma_tf32(acc[mi][ti], al[mi], bh0, bh1);
                mma_tf32(acc[mi][ti], ah[mi], bl0, bl1);
            }
        }
    }

    // epilogue
    int g = ln >> 2, tt = ln & 3;
#pragma unroll
    for (int mi = 0; mi < 2; mi++) {
        int row0 = bm + (wm * 2 + mi) * 16 + g;
        int row1 = row0 + 8;
#pragma unroll
        for (int ti = 0; ti < 8; ti++) {
            int col = (wn * 8 + ti) * 8 + tt * 2;
            if (row0 < M)
                *(float2*)(C + (size_t)row0 * 128 + col) = make_float2(acc[mi][ti][0], acc[mi][ti][1]);
            if (row1 < M)
                *(float2*)(C + (size_t)row1 * 128 + col) = make_float2(acc[mi][ti][2], acc[mi][ti][3]);
        }
    }
}

// ---------------- aggregation (+bias [+relu+LN | head]) ; warp per node ----------------
__global__ void k_agg(const float* __restrict__ lin, const float* __restrict__ bias,
                      const float* __restrict__ lng, const float* __restrict__ lnb,
                      float* __restrict__ outp, int doLN, float* __restrict__ logp) {
    int gtid = blockIdx.x * blockDim.x + threadIdx.x;
    int node = gtid >> 5;
    if (node >= NN) return;
    int lane = gtid & 31;

    float dn = g_dinv[node];
    const float4* rowp = (const float4*)(lin + (size_t)node * HD);
    float4 v = rowp[lane];
    float w0 = dn * dn;                       // self loop
    float4 acc = make_float4(v.x * w0, v.y * w0, v.z * w0, v.w * w0);

    int e0 = g_off[node], e1 = g_off[node + 1];
    int e = e0;
    for (; e + 8 <= e1; e += 8) {
        int s0 = g_csrc[e + 0];
        int s1 = g_csrc[e + 1];
        int s2 = g_csrc[e + 2];
        int s3 = g_csrc[e + 3];
        int s4 = g_csrc[e + 4];
        int s5 = g_csrc[e + 5];
        int s6 = g_csrc[e + 6];
        int s7 = g_csrc[e + 7];
        float w_0 = g_dinv[s0] * dn;
        float w_1 = g_dinv[s1] * dn;
        float w_2 = g_dinv[s2] * dn;
        float w_3 = g_dinv[s3] * dn;
        float w_4 = g_dinv[s4] * dn;
        float w_5 = g_dinv[s5] * dn;
        float w_6 = g_dinv[s6] * dn;
        float w_7 = g_dinv[s7] * dn;
        float4 u0 = ((const float4*)(lin + (size_t)s0 * HD))[lane];
        float4 u1 = ((const float4*)(lin + (size_t)s1 * HD))[lane];
        float4 u2 = ((const float4*)(lin + (size_t)s2 * HD))[lane];
        float4 u3 = ((const float4*)(lin + (size_t)s3 * HD))[lane];
        float4 u4 = ((const float4*)(lin + (size_t)s4 * HD))[lane];
        float4 u5 = ((const float4*)(lin + (size_t)s5 * HD))[lane];
        float4 u6 = ((const float4*)(lin + (size_t)s6 * HD))[lane];
        float4 u7 = ((const float4*)(lin + (size_t)s7 * HD))[lane];
        acc.x += u0.x * w_0; acc.y += u0.y * w_0; acc.z += u0.z * w_0; acc.w += u0.w * w_0;
        acc.x += u1.x * w_1; acc.y += u1.y * w_1; acc.z += u1.z * w_1; acc.w += u1.w * w_1;
        acc.x += u2.x * w_2; acc.y += u2.y * w_2; acc.z += u2.z * w_2; acc.w += u2.w * w_2;
        acc.x += u3.x * w_3; acc.y += u3.y * w_3; acc.z += u3.z * w_3; acc.w += u3.w * w_3;
        acc.x += u4.x * w_4; acc.y += u4.y * w_4; acc.z += u4.z * w_4; acc.w += u4.w * w_4;
        acc.x += u5.x * w_5; acc.y += u5.y * w_5; acc.z += u5.z * w_5; acc.w += u5.w * w_5;
        acc.x += u6.x * w_6; acc.y += u6.y * w_6; acc.z += u6.z * w_6; acc.w += u6.w * w_6;
        acc.x += u7.x * w_7; acc.y += u7.y * w_7; acc.z += u7.z * w_7; acc.w += u7.w * w_7;
    }
    for (; e < e1; e++) {
        int s = g_csrc[e];
        float w = g_dinv[s] * dn;
        float4 u = ((const float4*)(lin + (size_t)s * HD))[lane];
        acc.x += u.x * w; acc.y += u.y * w; acc.z += u.z * w; acc.w += u.w * w;
    }
    float4 bb = ((const float4*)bias)[lane];
    acc.x += bb.x; acc.y += bb.y; acc.z += bb.z; acc.w += bb.w;

    if (doLN) {
        acc.x = fmaxf(acc.x, 0.f); acc.y = fmaxf(acc.y, 0.f);
        acc.z = fmaxf(acc.z, 0.f); acc.w = fmaxf(acc.w, 0.f);
        float s1 = acc.x + acc.y + acc.z + acc.w;
        float s2 = acc.x * acc.x + acc.y * acc.y + acc.z * acc.z + acc.w * acc.w;
#pragma unroll
        for (int o = 16; o > 0; o >>= 1) {
            s1 += __shfl_xor_sync(0xffffffffu, s1, o);
            s2 += __shfl_xor_sync(0xffffffffu, s2, o);
        }
        float mu = s1 * (1.0f / HD);
        float var = s2 * (1.0f / HD) - mu * mu;
        float r = rsqrtf(var + EPSV);
        float4 gg = ((const float4*)lng)[lane];
        float4 bl = ((const float4*)lnb)[lane];
        acc.x = (acc.x - mu) * r * gg.x + bl.x;
        acc.y = (acc.y - mu) * r * gg.y + bl.y;
        acc.z = (acc.z - mu) * r * gg.z + bl.z;
        acc.w = (acc.w - mu) * r * gg.w + bl.w;
        ((float4*)(outp + (size_t)node * HD))[lane] = acc;
    } else {
        // layer 2: write emb, then fused MLP head + log_softmax
        ((float4*)(outp + (size_t)node * HD))[lane] = acc;
        float4 r = make_float4(fmaxf(acc.x, 0.f), fmaxf(acc.y, 0.f),
                               fmaxf(acc.z, 0.f), fmaxf(acc.w, 0.f));
        const float4* wp = (const float4*)g_Wc;
        float4 wa = wp[lane * 2];       // (k0c0,k0c1,k1c0,k1c1)
        float4 wb = wp[lane * 2 + 1];   // (k2c0,k2c1,k3c0,k3c1)
        float l0 = r.x * wa.x + r.y * wa.z + r.z * wb.x + r.w * wb.z;
        float l1 = r.x * wa.y + r.y * wa.w + r.z * wb.y + r.w * wb.w;
#pragma unroll
        for (int o = 16; o > 0; o >>= 1) {
            l0 += __shfl_xor_sync(0xffffffffu, l0, o);
            l1 += __shfl_xor_sync(0xffffffffu, l1, o);
        }
        if (lane == 0) {
            l0 += g_bc[0]; l1 += g_bc[1];
            float m = fmaxf(l0, l1);
            float lse = m + logf(expf(l0 - m) + expf(l1 - m));
            logp[(size_t)node * 2 + 0] = l0 - lse;
            logp[(size_t)node * 2 + 1] = l1 - lse;
        }
    }
}

// ---------------- MLP head collapse: Wc = W1@W2 [128,2], bc = b1@W2 + b2 ----------------
__global__ void k_compose(const float* __restrict__ mpW1, const float* __restrict__ mpW2,
                          const float* __restrict__ mpb1, const float* __restrict__ mpb2) {
    int t = threadIdx.x;     // 256
    int k = t >> 1, c = t & 1;
    float s = 0.f;
    for (int j = 0; j < 128; j++) s += mpW1[k * 128 + j] * mpW2[j * 2 + c];
    g_Wc[k * 2 + c] = s;
    if (t < 2) {
        float sb = 0.f;
        for (int j = 0; j < 128; j++) sb += mpb1[j] * mpW2[j * 2 + t];
        g_bc[t] = sb + mpb2[t];
    }
}

// ---------------- launch ----------------
extern "C" void kernel_launch(void* const* d_in, const int* in_sizes, int n_in,
                              void* d_out, int out_size) {
    const float* x    = (const float*)d_in[0];
    const int*   ei   = (const int*)d_in[1];
    const int*   srcI = ei;
    const int*   dstI = ei + NE;
    const float* W1 = (const float*)d_in[2];
    const float* b1 = (const float*)d_in[3];
    const float* W2 = (const float*)d_in[4];
    const float* b2 = (const float*)d_in[5];
    const float* W3 = (const float*)d_in[6];
    const float* b3 = (const float*)d_in[7];
    const float* ln1g = (const float*)d_in[8];
    const float* ln1b = (const float*)d_in[9];
    const float* ln2g = (const float*)d_in[10];
    const float* ln2b = (const float*)d_in[11];
    const float* mpW1 = (const float*)d_in[12];
    const float* mpb1 = (const float*)d_in[13];
    const float* mpW2 = (const float*)d_in[14];
    const float* mpb2 = (const float*)d_in[15];

    float* out  = (float*)d_out;
    float* emb  = out;                      // [NN,128]
    float* logp = out + (size_t)NN * HD;    // [NN,2]

    float *bufA, *bufB;
    cudaGetSymbolAddress((void**)&bufA, g_bufA);
    cudaGetSymbolAddress((void**)&bufB, g_bufB);

    // unconditional (no static guards); not a stream op -> capture-safe
    cudaFuncSetAttribute(gemm_tc, cudaFuncAttributeMaxDynamicSharedMemorySize, 131072);

    // graph preprocessing (per launch; deterministic)
    k_zero<<<(NN + 255) / 256, 256>>>();
    k_count<<<(NE + 255) / 256, 256>>>(dstI);
    k_scan<<<1, 1024>>>();
    k_scatter<<<(NE + 255) / 256, 256>>>(srcI, dstI);
    k_compose<<<1, 256>>>(mpW1, mpW2, mpb1, mpb2);

    int gemmBlocks = (NN + 127) / 128;
    int aggBlocks = (NN * 32 + 255) / 256;

    // layer 0
    gemm_tc<<<gemmBlocks, 256, 131072>>>(x, W1, bufA, NN);
    k_agg<<<aggBlocks, 256>>>(bufA, b1, ln1g, ln1b, bufB, 1, nullptr);
    // layer 1
    gemm_tc<<<gemmBlocks, 256, 131072>>>(bufB, W2, bufA, NN);
    k_agg<<<aggBlocks, 256>>>(bufA, b2, ln2g, ln2b, bufB, 1, nullptr);
    // layer 2 -> emb + fused head
    gemm_tc<<<gemmBlocks, 256, 131072>>>(bufB, W3, bufA, NN);
    k_agg<<<aggBlocks, 256>>>(bufA, b3, nullptr, nullptr, emb, 0, logp);
}

// round 11
// speedup vs baseline: 1.3257x; 1.3257x over previous
#include <cuda_runtime.h>
#include <math.h>
#include <stdint.h>

#define NN 100000
#define NE 1600000
#define HD 128
#define EPSV 1e-5f

// ---------------- scratch (static device globals; no allocation) ----------------
__device__ int   g_deg[NN];
__device__ int   g_fill[NN];
__device__ int   g_off[NN + 1];
__device__ float g_dinv[NN];
__device__ int   g_csrc[NE];
__device__ float g_bufA[(size_t)NN * HD];
__device__ float g_bufB[(size_t)NN * HD];
__device__ float g_Wc[HD * 2];
__device__ float g_bc[2];
// B fragments (hi/lo TF32), order: [ntile 16][k 16][lane 32]
__device__ uint2 g_bH[3][8192];
__device__ uint2 g_bL[3][8192];

// ---------------- graph preprocessing ----------------
__global__ void k_zero() {
    int i = blockIdx.x * blockDim.x + threadIdx.x;
    if (i < NN) { g_deg[i] = 0; g_fill[i] = 0; }
}

__global__ void k_count(const int* __restrict__ dst) {
    int i = blockIdx.x * blockDim.x + threadIdx.x;
    if (i < NE) atomicAdd(&g_deg[dst[i]], 1);
}

__global__ void k_scan() {
    __shared__ int ss[1024];
    const int T = 1024;
    const int CH = (NN + T - 1) / T;
    int t = threadIdx.x;
    int lo = t * CH; if (lo > NN) lo = NN;
    int hi = lo + CH; if (hi > NN) hi = NN;
    int s = 0;
    for (int i = lo; i < hi; i++) s += g_deg[i];
    ss[t] = s;
    __syncthreads();
    for (int d = 1; d < T; d <<= 1) {
        int v = (t >= d) ? ss[t - d] : 0;
        __syncthreads();
        ss[t] += v;
        __syncthreads();
    }
    int run = (t == 0) ? 0 : ss[t - 1];
    for (int i = lo; i < hi; i++) {
        g_off[i] = run;
        int dg = g_deg[i];
        run += dg;
        g_dinv[i] = rsqrtf((float)(dg + 1));
    }
    if (t == T - 1) g_off[NN] = run;
}

__global__ void k_scatter(const int* __restrict__ src, const int* __restrict__ dst) {
    int i = blockIdx.x * blockDim.x + threadIdx.x;
    if (i < NE) {
        int d = dst[i];
        int p = g_off[d] + atomicAdd(&g_fill[d], 1);
        g_csrc[p] = src[i];
    }
}

// ---------------- TF32 helpers ----------------
__device__ __forceinline__ uint32_t f2tf(float f) {
    uint32_t u;
    asm("cvt.rna.tf32.f32 %0, %1;" : "=r"(u) : "f"(f));
    return u;
}
__device__ __forceinline__ void mma_tf32(float* d, const uint32_t* a, uint32_t b0, uint32_t b1) {
    asm volatile(
        "mma.sync.aligned.m16n8k8.row.col.f32.tf32.tf32.f32 "
        "{%0,%1,%2,%3}, {%4,%5,%6,%7}, {%8,%9}, {%0,%1,%2,%3};"
        : "+f"(d[0]), "+f"(d[1]), "+f"(d[2]), "+f"(d[3])
        : "r"(a[0]), "r"(a[1]), "r"(a[2]), "r"(a[3]), "r"(b0), "r"(b1));
}

// precompute B fragments (hi/lo) in warp consumption order; 32 blocks x 256 thr per matrix
__global__ void k_bfrag(const float* __restrict__ W, int mat) {
    int s = blockIdx.x * blockDim.x + threadIdx.x;   // 0..8191
    if (s >= 8192) return;
    int t  = s >> 9;          // n-tile
    int k  = (s >> 5) & 15;   // k-step
    int ln = s & 31;
    int g = ln >> 2, tt = ln & 3;
    int r0 = k * 8 + tt, c = t * 8 + g;
    float b0 = W[r0 * 128 + c];
    float b1 = W[(r0 + 4) * 128 + c];
    uint32_t h0 = f2tf(b0), h1 = f2tf(b1);
    g_bH[mat][s] = make_uint2(h0, h1);
    g_bL[mat][s] = make_uint2(f2tf(b0 - __uint_as_float(h0)), f2tf(b1 - __uint_as_float(h1)));
}

// ---------------- tensor-core TF32 GEMM: C[M,128] = A[M,128]@B ----------------
// 256 thr / 8 warps; 128 rows per block; smem A [128][132] fp32 (66KB, 2 CTA/SM)
__global__ __launch_bounds__(256, 2) void gemm_tc(const float* __restrict__ A,
                                                  const uint2* __restrict__ bh,
                                                  const uint2* __restrict__ bl,
                                                  float* __restrict__ C, int M) {
    extern __shared__ float smA[];   // [128][132]
    int tid = threadIdx.x;
    int bm = blockIdx.x * 128;

    // coalesced A staging
    for (int s = tid; s < 128 * 32; s += 256) {
        int row = s >> 5, c4 = (s & 31) * 4;
        int gr = bm + row;
        float4 v = (gr < M) ? *(const float4*)(A + (size_t)gr * 128 + c4)
                            : make_float4(0.f, 0.f, 0.f, 0.f);
        *(float4*)&smA[row * 132 + c4] = v;
    }
    __syncthreads();

    int wid = tid >> 5, ln = tid & 31;
    int wm = wid & 3;    // m-tiles wm*2, wm*2+1
    int wn = wid >> 2;   // n-tiles wn*8 .. +7
    int g = ln >> 2, tt = ln & 3;

    float acc[2][8][4] = {};

#pragma unroll
    for (int k = 0; k < 16; k++) {
        uint32_t ah[2][4], al[2][4];
#pragma unroll
        for (int mi = 0; mi < 2; mi++) {
            int row0 = (wm * 2 + mi) * 16 + g;
            float a0 = smA[row0 * 132 + k * 8 + tt];
            float a1 = smA[(row0 + 8) * 132 + k * 8 + tt];
            float a2 = smA[row0 * 132 + k * 8 + tt + 4];
            float a3 = smA[(row0 + 8) * 132 + k * 8 + tt + 4];
            ah[mi][0] = f2tf(a0); al[mi][0] = f2tf(a0 - __uint_as_float(ah[mi][0]));
            ah[mi][1] = f2tf(a1); al[mi][1] = f2tf(a1 - __uint_as_float(ah[mi][1]));
            ah[mi][2] = f2tf(a2); al[mi][2] = f2tf(a2 - __uint_as_float(ah[mi][2]));
            ah[mi][3] = f2tf(a3); al[mi][3] = f2tf(a3 - __uint_as_float(ah[mi][3]));
        }
#pragma unroll
        for (int ti = 0; ti < 8; ti++) {
            int idx = ((wn * 8 + ti) * 16 + k) * 32 + ln;
            uint2 H = bh[idx];
            uint2 L = bl[idx];
#pragma unroll
            for (int mi = 0; mi < 2; mi++) {
                mma_tf32(acc[mi][ti], ah[mi], H.x, H.y);
                mma_tf32(acc[mi][ti], al[mi], H.x, H.y);
                mma_tf32(acc[mi][ti], ah[mi], L.x, L.y);
            }
        }
    }

    // epilogue
#pragma unroll
    for (int mi = 0; mi < 2; mi++) {
        int row0 = bm + (wm * 2 + mi) * 16 + g;
        int row1 = row0 + 8;
#pragma unroll
        for (int ti = 0; ti < 8; ti++) {
            int col = (wn * 8 + ti) * 8 + tt * 2;
            if (row0 < M)
                *(float2*)(C + (size_t)row0 * 128 + col) = make_float2(acc[mi][ti][0], acc[mi][ti][1]);
            if (row1 < M)
                *(float2*)(C + (size_t)row1 * 128 + col) = make_float2(acc[mi][ti][2], acc[mi][ti][3]);
        }
    }
}

// ---------------- aggregation (+bias [+relu+LN | head]) ; warp per node ----------------
__global__ void k_agg(const float* __restrict__ lin, const float* __restrict__ bias,
                      const float* __restrict__ lng, const float* __restrict__ lnb,
                      float* __restrict__ outp, int doLN, float* __restrict__ logp) {
    int gtid = blockIdx.x * blockDim.x + threadIdx.x;
    int node = gtid >> 5;
    if (node >= NN) return;
    int lane = gtid & 31;

    float dn = g_dinv[node];
    const float4* rowp = (const float4*)(lin + (size_t)node * HD);
    float4 v = rowp[lane];
    float w0 = dn * dn;
    float4 acc = make_float4(v.x * w0, v.y * w0, v.z * w0, v.w * w0);

    int e0 = g_off[node], e1 = g_off[node + 1];
    int e = e0;
    for (; e + 8 <= e1; e += 8) {
        int s0 = g_csrc[e + 0];
        int s1 = g_csrc[e + 1];
        int s2 = g_csrc[e + 2];
        int s3 = g_csrc[e + 3];
        int s4 = g_csrc[e + 4];
        int s5 = g_csrc[e + 5];
        int s6 = g_csrc[e + 6];
        int s7 = g_csrc[e + 7];
        float w_0 = g_dinv[s0] * dn;
        float w_1 = g_dinv[s1] * dn;
        float w_2 = g_dinv[s2] * dn;
        float w_3 = g_dinv[s3] * dn;
        float w_4 = g_dinv[s4] * dn;
        float w_5 = g_dinv[s5] * dn;
        float w_6 = g_dinv[s6] * dn;
        float w_7 = g_dinv[s7] * dn;
        float4 u0 = ((const float4*)(lin + (size_t)s0 * HD))[lane];
        float4 u1 = ((const float4*)(lin + (size_t)s1 * HD))[lane];
        float4 u2 = ((const float4*)(lin + (size_t)s2 * HD))[lane];
        float4 u3 = ((const float4*)(lin + (size_t)s3 * HD))[lane];
        float4 u4 = ((const float4*)(lin + (size_t)s4 * HD))[lane];
        float4 u5 = ((const float4*)(lin + (size_t)s5 * HD))[lane];
        float4 u6 = ((const float4*)(lin + (size_t)s6 * HD))[lane];
        float4 u7 = ((const float4*)(lin + (size_t)s7 * HD))[lane];
        acc.x += u0.x * w_0; acc.y += u0.y * w_0; acc.z += u0.z * w_0; acc.w += u0.w * w_0;
        acc.x += u1.x * w_1; acc.y += u1.y * w_1; acc.z += u1.z * w_1; acc.w += u1.w * w_1;
        acc.x += u2.x * w_2; acc.y += u2.y * w_2; acc.z += u2.z * w_2; acc.w += u2.w * w_2;
        acc.x += u3.x * w_3; acc.y += u3.y * w_3; acc.z += u3.z * w_3; acc.w += u3.w * w_3;
        acc.x += u4.x * w_4; acc.y += u4.y * w_4; acc.z += u4.z * w_4; acc.w += u4.w * w_4;
        acc.x += u5.x * w_5; acc.y += u5.y * w_5; acc.z += u5.z * w_5; acc.w += u5.w * w_5;
        acc.x += u6.x * w_6; acc.y += u6.y * w_6; acc.z += u6.z * w_6; acc.w += u6.w * w_6;
        acc.x += u7.x * w_7; acc.y += u7.y * w_7; acc.z += u7.z * w_7; acc.w += u7.w * w_7;
    }
    for (; e < e1; e++) {
        int s = g_csrc[e];
        float w = g_dinv[s] * dn;
        float4 u = ((const float4*)(lin + (size_t)s * HD))[lane];
        acc.x += u.x * w; acc.y += u.y * w; acc.z += u.z * w; acc.w += u.w * w;
    }
    float4 bb = ((const float4*)bias)[lane];
    acc.x += bb.x; acc.y += bb.y; acc.z += bb.z; acc.w += bb.w;

    if (doLN) {
        acc.x = fmaxf(acc.x, 0.f); acc.y = fmaxf(acc.y, 0.f);
        acc.z = fmaxf(acc.z, 0.f); acc.w = fmaxf(acc.w, 0.f);
        float s1 = acc.x + acc.y + acc.z + acc.w;
        float s2 = acc.x * acc.x + acc.y * acc.y + acc.z * acc.z + acc.w * acc.w;
#pragma unroll
        for (int o = 16; o > 0; o >>= 1) {
            s1 += __shfl_xor_sync(0xffffffffu, s1, o);
            s2 += __shfl_xor_sync(0xffffffffu, s2, o);
        }
        float mu = s1 * (1.0f / HD);
        float var = s2 * (1.0f / HD) - mu * mu;
        float r = rsqrtf(var + EPSV);
        float4 gg = ((const float4*)lng)[lane];
        float4 bl = ((const float4*)lnb)[lane];
        acc.x = (acc.x - mu) * r * gg.x + bl.x;
        acc.y = (acc.y - mu) * r * gg.y + bl.y;
        acc.z = (acc.z - mu) * r * gg.z + bl.z;
        acc.w = (acc.w - mu) * r * gg.w + bl.w;
        ((float4*)(outp + (size_t)node * HD))[lane] = acc;
    } else {
        ((float4*)(outp + (size_t)node * HD))[lane] = acc;
        float4 r = make_float4(fmaxf(acc.x, 0.f), fmaxf(acc.y, 0.f),
                               fmaxf(acc.z, 0.f), fmaxf(acc.w, 0.f));
        const float4* wp = (const float4*)g_Wc;
        float4 wa = wp[lane * 2];
        float4 wb = wp[lane * 2 + 1];
        float l0 = r.x * wa.x + r.y * wa.z + r.z * wb.x + r.w * wb.z;
        float l1 = r.x * wa.y + r.y * wa.w + r.z * wb.y + r.w * wb.w;
#pragma unroll
        for (int o = 16; o > 0; o >>= 1) {
            l0 += __shfl_xor_sync(0xffffffffu, l0, o);
            l1 += __shfl_xor_sync(0xffffffffu, l1, o);
        }
        if (lane == 0) {
            l0 += g_bc[0]; l1 += g_bc[1];
            float m = fmaxf(l0, l1);
            float lse = m + logf(expf(l0 - m) + expf(l1 - m));
            logp[(size_t)node * 2 + 0] = l0 - lse;
            logp[(size_t)node * 2 + 1] = l1 - lse;
        }
    }
}

// ---------------- MLP head collapse ----------------
__global__ void k_compose(const float* __restrict__ mpW1, const float* __restrict__ mpW2,
                          const float* __restrict__ mpb1, const float* __restrict__ mpb2) {
    int t = threadIdx.x;
    int k = t >> 1, c = t & 1;
    float s = 0.f;
    for (int j = 0; j < 128; j++) s += mpW1[k * 128 + j] * mpW2[j * 2 + c];
    g_Wc[k * 2 + c] = s;
    if (t < 2) {
        float sb = 0.f;
        for (int j = 0; j < 128; j++) sb += mpb1[j] * mpW2[j * 2 + t];
        g_bc[t] = sb + mpb2[t];
    }
}

// ---------------- launch ----------------
extern "C" void kernel_launch(void* const* d_in, const int* in_sizes, int n_in,
                              void* d_out, int out_size) {
    const float* x    = (const float*)d_in[0];
    const int*   ei   = (const int*)d_in[1];
    const int*   srcI = ei;
    const int*   dstI = ei + NE;
    const float* W1 = (const float*)d_in[2];
    const float* b1 = (const float*)d_in[3];
    const float* W2 = (const float*)d_in[4];
    const float* b2 = (const float*)d_in[5];
    const float* W3 = (const float*)d_in[6];
    const float* b3 = (const float*)d_in[7];
    const float* ln1g = (const float*)d_in[8];
    const float* ln1b = (const float*)d_in[9];
    const float* ln2g = (const float*)d_in[10];
    const float* ln2b = (const float*)d_in[11];
    const float* mpW1 = (const float*)d_in[12];
    const float* mpb1 = (const float*)d_in[13];
    const float* mpW2 = (const float*)d_in[14];
    const float* mpb2 = (const float*)d_in[15];

    float* out  = (float*)d_out;
    float* emb  = out;
    float* logp = out + (size_t)NN * HD;

    float *bufA, *bufB;
    cudaGetSymbolAddress((void**)&bufA, g_bufA);
    cudaGetSymbolAddress((void**)&bufB, g_bufB);
    uint2 *bH, *bL;
    cudaGetSymbolAddress((void**)&bH, g_bH);
    cudaGetSymbolAddress((void**)&bL, g_bL);

    cudaFuncSetAttribute(gemm_tc, cudaFuncAttributeMaxDynamicSharedMemorySize, 128 * 132 * 4);

    // graph preprocessing
    k_zero<<<(NN + 255) / 256, 256>>>();
    k_count<<<(NE + 255) / 256, 256>>>(dstI);
    k_scan<<<1, 1024>>>();
    k_scatter<<<(NE + 255) / 256, 256>>>(srcI, dstI);
    k_compose<<<1, 256>>>(mpW1, mpW2, mpb1, mpb2);
    k_bfrag<<<32, 256>>>(W1, 0);
    k_bfrag<<<32, 256>>>(W2, 1);
    k_bfrag<<<32, 256>>>(W3, 2);

    int gemmBlocks = (NN + 127) / 128;
    int aggBlocks = (NN * 32 + 255) / 256;
    int smemSz = 128 * 132 * 4;

    // layer 0
    gemm_tc<<<gemmBlocks, 256, smemSz>>>(x, bH, bL, bufA, NN);
    k_agg<<<aggBlocks, 256>>>(bufA, b1, ln1g, ln1b, bufB, 1, nullptr);
    // layer 1
    gemm_tc<<<gemmBlocks, 256, smemSz>>>(bufB, bH + 8192, bL + 8192, bufA, NN);
    k_agg<<<aggBlocks, 256>>>(bufA, b2, ln2g, ln2b, bufB, 1, nullptr);
    // layer 2 -> emb + fused head
    gemm_tc<<<gemmBlocks, 256, smemSz>>>(bufB, bH + 16384, bL + 16384, bufA, NN);
    k_agg<<<aggBlocks, 256>>>(bufA, b3, nullptr, nullptr, emb, 0, logp);
}

// round 13
// speedup vs baseline: 1.4146x; 1.0670x over previous
#include <cuda_runtime.h>
#include <cuda_bf16.h>
#include <math.h>
#include <stdint.h>

#define NN 100000
#define NE 1600000
#define HD 128
#define EPSV 1e-5f
#define SMA_STRIDE 136

// ---------------- scratch (static device globals; no allocation) ----------------
__device__ int   g_deg[NN];
__device__ int   g_fill[NN];
__device__ int   g_off[NN + 1];
__device__ float g_dinv[NN];
__device__ int   g_csrc[NE];
__device__ float g_bufA[(size_t)NN * HD];
__device__ float g_bufB[(size_t)NN * HD];
__device__ float g_Wc[HD * 2];
__device__ float g_bc[2];
// B fragments (hi/lo bf16x2 pairs), order: [ntile 16][k 8][lane 32]
__device__ uint2 g_bH[3][4096];
__device__ uint2 g_bL[3][4096];

// ---------------- graph preprocessing ----------------
__global__ void k_zero() {
    int i = blockIdx.x * blockDim.x + threadIdx.x;
    if (i < NN) { g_deg[i] = 0; g_fill[i] = 0; }
}

__global__ void k_count(const int* __restrict__ dst) {
    int i = blockIdx.x * blockDim.x + threadIdx.x;
    if (i < NE) atomicAdd(&g_deg[dst[i]], 1);
}

__global__ void k_scan() {
    __shared__ int ss[1024];
    const int T = 1024;
    const int CH = (NN + T - 1) / T;
    int t = threadIdx.x;
    int lo = t * CH; if (lo > NN) lo = NN;
    int hi = lo + CH; if (hi > NN) hi = NN;
    int s = 0;
    for (int i = lo; i < hi; i++) s += g_deg[i];
    ss[t] = s;
    __syncthreads();
    for (int d = 1; d < T; d <<= 1) {
        int v = (t >= d) ? ss[t - d] : 0;
        __syncthreads();
        ss[t] += v;
        __syncthreads();
    }
    int run = (t == 0) ? 0 : ss[t - 1];
    for (int i = lo; i < hi; i++) {
        g_off[i] = run;
        int dg = g_deg[i];
        run += dg;
        g_dinv[i] = rsqrtf((float)(dg + 1));
    }
    if (t == T - 1) g_off[NN] = run;
}

__global__ void k_scatter(const int* __restrict__ src, const int* __restrict__ dst) {
    int i = blockIdx.x * blockDim.x + threadIdx.x;
    if (i < NE) {
        int d = dst[i];
        int p = g_off[d] + atomicAdd(&g_fill[d], 1);
        g_csrc[p] = src[i];
    }
}

// ---------------- bf16 split helpers ----------------
__device__ __forceinline__ uint32_t pack_bf16_hi(float a, float b) {
    // a -> low half, b -> high half
    __nv_bfloat162 p = __floats2bfloat162_rn(a, b);
    return *(uint32_t*)&p;
}
__device__ __forceinline__ float bf16_resid(float x) {
    return x - __bfloat162float(__float2bfloat16_rn(x));
}
__device__ __forceinline__ void mma_bf16(float* d, const uint32_t* a, uint32_t b0, uint32_t b1) {
    asm volatile(
        "mma.sync.aligned.m16n8k16.row.col.f32.bf16.bf16.f32 "
        "{%0,%1,%2,%3}, {%4,%5,%6,%7}, {%8,%9}, {%0,%1,%2,%3};"
        : "+f"(d[0]), "+f"(d[1]), "+f"(d[2]), "+f"(d[3])
        : "r"(a[0]), "r"(a[1]), "r"(a[2]), "r"(a[3]), "r"(b0), "r"(b1));
}

// precompute B fragments (hi/lo bf16x2) in warp consumption order
// s: [ntile 16][kchunk 8][lane 32] = 4096 per matrix
__global__ void k_bfrag(const float* __restrict__ W, int mat) {
    int s = blockIdx.x * blockDim.x + threadIdx.x;
    if (s >= 4096) return;
    int ti = s >> 8;          // n-tile 0..15
    int k  = (s >> 5) & 7;    // k-chunk 0..7
    int ln = s & 31;
    int g = ln >> 2, tt = ln & 3;
    int c = ti * 8 + g;
    int r0 = k * 16 + 2 * tt;       // b0: k = 2tt, 2tt+1
    int r1 = k * 16 + 2 * tt + 8;   // b1: k = 2tt+8, 2tt+9
    float v00 = W[r0 * 128 + c],       v01 = W[(r0 + 1) * 128 + c];
    float v10 = W[r1 * 128 + c],       v11 = W[(r1 + 1) * 128 + c];
    g_bH[mat][s] = make_uint2(pack_bf16_hi(v00, v01), pack_bf16_hi(v10, v11));
    g_bL[mat][s] = make_uint2(pack_bf16_hi(bf16_resid(v00), bf16_resid(v01)),
                              pack_bf16_hi(bf16_resid(v10), bf16_resid(v11)));
}

// ---------------- tensor-core bf16 (3-term split) GEMM: C[M,128] = A[M,128]@B ----
// 256 thr / 8 warps; 128 rows per block; smem A [128][136] fp32 (~69.6KB, 2 CTA/SM)
__global__ __launch_bounds__(256, 2) void gemm_tc(const float* __restrict__ A,
                                                  const uint2* __restrict__ bh,
                                                  const uint2* __restrict__ bl,
                                                  float* __restrict__ C, int M) {
    extern __shared__ float smA[];   // [128][SMA_STRIDE]
    int tid = threadIdx.x;
    int bm = blockIdx.x * 128;

    // coalesced A staging
    for (int s = tid; s < 128 * 32; s += 256) {
        int row = s >> 5, c4 = (s & 31) * 4;
        int gr = bm + row;
        float4 v = (gr < M) ? *(const float4*)(A + (size_t)gr * 128 + c4)
                            : make_float4(0.f, 0.f, 0.f, 0.f);
        *(float4*)&smA[row * SMA_STRIDE + c4] = v;
    }
    __syncthreads();

    int wid = tid >> 5, ln = tid & 31;
    int wm = wid & 3;    // m-tiles wm*2, wm*2+1
    int wn = wid >> 2;   // n-tiles wn*8 .. +7
    int g = ln >> 2, tt = ln & 3;

    float acc[2][8][4] = {};

#pragma unroll
    for (int k = 0; k < 8; k++) {        // k-chunks of 16
        uint32_t ah[2][4], al[2][4];
#pragma unroll
        for (int mi = 0; mi < 2; mi++) {
            int row0 = (wm * 2 + mi) * 16 + g;
            int cA = k * 16 + tt * 2;
            float2 f00 = *(const float2*)&smA[row0 * SMA_STRIDE + cA];            // a0: (row0, cA..cA+1)
            float2 f10 = *(const float2*)&smA[(row0 + 8) * SMA_STRIDE + cA];      // a1
            float2 f02 = *(const float2*)&smA[row0 * SMA_STRIDE + cA + 8];        // a2
            float2 f12 = *(const float2*)&smA[(row0 + 8) * SMA_STRIDE + cA + 8];  // a3
            ah[mi][0] = pack_bf16_hi(f00.x, f00.y);
            ah[mi][1] = pack_bf16_hi(f10.x, f10.y);
            ah[mi][2] = pack_bf16_hi(f02.x, f02.y);
            ah[mi][3] = pack_bf16_hi(f12.x, f12.y);
            al[mi][0] = pack_bf16_hi(bf16_resid(f00.x), bf16_resid(f00.y));
            al[mi][1] = pack_bf16_hi(bf16_resid(f10.x), bf16_resid(f10.y));
            al[mi][2] = pack_bf16_hi(bf16_resid(f02.x), bf16_resid(f02.y));
            al[mi][3] = pack_bf16_hi(bf16_resid(f12.x), bf16_resid(f12.y));
        }
#pragma unroll
        for (int ti = 0; ti < 8; ti++) {
            int idx = ((wn * 8 + ti) * 8 + k) * 32 + ln;
            uint2 H = bh[idx];
            uint2 L = bl[idx];
#pragma unroll
            for (int mi = 0; mi < 2; mi++) {
                mma_bf16(acc[mi][ti], ah[mi], H.x, H.y);   // ah*bh
                mma_bf16(acc[mi][ti], al[mi], H.x, H.y);   // al*bh
                mma_bf16(acc[mi][ti], ah[mi], L.x, L.y);   // ah*bl
            }
        }
    }

    // epilogue (C frag: {c0,c1}=(g, 2tt..2tt+1), {c2,c3}=(g+8, ...))
#pragma unroll
    for (int mi = 0; mi < 2; mi++) {
        int row0 = bm + (wm * 2 + mi) * 16 + g;
        int row1 = row0 + 8;
#pragma unroll
        for (int ti = 0; ti < 8; ti++) {
            int col = (wn * 8 + ti) * 8 + tt * 2;
            if (row0 < M)
                *(float2*)(C + (size_t)row0 * 128 + col) = make_float2(acc[mi][ti][0], acc[mi][ti][1]);
            if (row1 < M)
                *(float2*)(C + (size_t)row1 * 128 + col) = make_float2(acc[mi][ti][2], acc[mi][ti][3]);
        }
    }
}

// ---------------- aggregation (+bias [+relu+LN | head]) ; warp per node ----------------
__global__ void k_agg(const float* __restrict__ lin, const float* __restrict__ bias,
                      const float* __restrict__ lng, const float* __restrict__ lnb,
                      float* __restrict__ outp, int doLN, float* __restrict__ logp) {
    int gtid = blockIdx.x * blockDim.x + threadIdx.x;
    int node = gtid >> 5;
    if (node >= NN) return;
    int lane = gtid & 31;

    float dn = g_dinv[node];
    const float4* rowp = (const float4*)(lin + (size_t)node * HD);
    float4 v = rowp[lane];
    float w0 = dn * dn;
    float4 acc = make_float4(v.x * w0, v.y * w0, v.z * w0, v.w * w0);

    int e0 = g_off[node], e1 = g_off[node + 1];
    int e = e0;
    for (; e + 8 <= e1; e += 8) {
        int s0 = g_csrc[e + 0];
        int s1 = g_csrc[e + 1];
        int s2 = g_csrc[e + 2];
        int s3 = g_csrc[e + 3];
        int s4 = g_csrc[e + 4];
        int s5 = g_csrc[e + 5];
        int s6 = g_csrc[e + 6];
        int s7 = g_csrc[e + 7];
        float w_0 = g_dinv[s0] * dn;
        float w_1 = g_dinv[s1] * dn;
        float w_2 = g_dinv[s2] * dn;
        float w_3 = g_dinv[s3] * dn;
        float w_4 = g_dinv[s4] * dn;
        float w_5 = g_dinv[s5] * dn;
        float w_6 = g_dinv[s6] * dn;
        float w_7 = g_dinv[s7] * dn;
        float4 u0 = ((const float4*)(lin + (size_t)s0 * HD))[lane];
        float4 u1 = ((const float4*)(lin + (size_t)s1 * HD))[lane];
        float4 u2 = ((const float4*)(lin + (size_t)s2 * HD))[lane];
        float4 u3 = ((const float4*)(lin + (size_t)s3 * HD))[lane];
        float4 u4 = ((const float4*)(lin + (size_t)s4 * HD))[lane];
        float4 u5 = ((const float4*)(lin + (size_t)s5 * HD))[lane];
        float4 u6 = ((const float4*)(lin + (size_t)s6 * HD))[lane];
        float4 u7 = ((const float4*)(lin + (size_t)s7 * HD))[lane];
        acc.x += u0.x * w_0; acc.y += u0.y * w_0; acc.z += u0.z * w_0; acc.w += u0.w * w_0;
        acc.x += u1.x * w_1; acc.y += u1.y * w_1; acc.z += u1.z * w_1; acc.w += u1.w * w_1;
        acc.x += u2.x * w_2; acc.y += u2.y * w_2; acc.z += u2.z * w_2; acc.w += u2.w * w_2;
        acc.x += u3.x * w_3; acc.y += u3.y * w_3; acc.z += u3.z * w_3; acc.w += u3.w * w_3;
        acc.x += u4.x * w_4; acc.y += u4.y * w_4; acc.z += u4.z * w_4; acc.w += u4.w * w_4;
        acc.x += u5.x * w_5; acc.y += u5.y * w_5; acc.z += u5.z * w_5; acc.w += u5.w * w_5;
        acc.x += u6.x * w_6; acc.y += u6.y * w_6; acc.z += u6.z * w_6; acc.w += u6.w * w_6;
        acc.x += u7.x * w_7; acc.y += u7.y * w_7; acc.z += u7.z * w_7; acc.w += u7.w * w_7;
    }
    for (; e < e1; e++) {
        int s = g_csrc[e];
        float w = g_dinv[s] * dn;
        float4 u = ((const float4*)(lin + (size_t)s * HD))[lane];
        acc.x += u.x * w; acc.y += u.y * w; acc.z += u.z * w; acc.w += u.w * w;
    }
    float4 bb = ((const float4*)bias)[lane];
    acc.x += bb.x; acc.y += bb.y; acc.z += bb.z; acc.w += bb.w;

    if (doLN) {
        acc.x = fmaxf(acc.x, 0.f); acc.y = fmaxf(acc.y, 0.f);
        acc.z = fmaxf(acc.z, 0.f); acc.w = fmaxf(acc.w, 0.f);
        float s1 = acc.x + acc.y + acc.z + acc.w;
        float s2 = acc.x * acc.x + acc.y * acc.y + acc.z * acc.z + acc.w * acc.w;
#pragma unroll
        for (int o = 16; o > 0; o >>= 1) {
            s1 += __shfl_xor_sync(0xffffffffu, s1, o);
            s2 += __shfl_xor_sync(0xffffffffu, s2, o);
        }
        float mu = s1 * (1.0f / HD);
        float var = s2 * (1.0f / HD) - mu * mu;
        float r = rsqrtf(var + EPSV);
        float4 gg = ((const float4*)lng)[lane];
        float4 bl = ((const float4*)lnb)[lane];
        acc.x = (acc.x - mu) * r * gg.x + bl.x;
        acc.y = (acc.y - mu) * r * gg.y + bl.y;
        acc.z = (acc.z - mu) * r * gg.z + bl.z;
        acc.w = (acc.w - mu) * r * gg.w + bl.w;
        ((float4*)(outp + (size_t)node * HD))[lane] = acc;
    } else {
        ((float4*)(outp + (size_t)node * HD))[lane] = acc;
        float4 r = make_float4(fmaxf(acc.x, 0.f), fmaxf(acc.y, 0.f),
                               fmaxf(acc.z, 0.f), fmaxf(acc.w, 0.f));
        const float4* wp = (const float4*)g_Wc;
        float4 wa = wp[lane * 2];
        float4 wb = wp[lane * 2 + 1];
        float l0 = r.x * wa.x + r.y * wa.z + r.z * wb.x + r.w * wb.z;
        float l1 = r.x * wa.y + r.y * wa.w + r.z * wb.y + r.w * wb.w;
#pragma unroll
        for (int o = 16; o > 0; o >>= 1) {
            l0 += __shfl_xor_sync(0xffffffffu, l0, o);
            l1 += __shfl_xor_sync(0xffffffffu, l1, o);
        }
        if (lane == 0) {
            l0 += g_bc[0]; l1 += g_bc[1];
            float m = fmaxf(l0, l1);
            float lse = m + logf(expf(l0 - m) + expf(l1 - m));
            logp[(size_t)node * 2 + 0] = l0 - lse;
            logp[(size_t)node * 2 + 1] = l1 - lse;
        }
    }
}

// ---------------- MLP head collapse ----------------
__global__ void k_compose(const float* __restrict__ mpW1, const float* __restrict__ mpW2,
                          const float* __restrict__ mpb1, const float* __restrict__ mpb2) {
    int t = threadIdx.x;
    int k = t >> 1, c = t & 1;
    float s = 0.f;
    for (int j = 0; j < 128; j++) s += mpW1[k * 128 + j] * mpW2[j * 2 + c];
    g_Wc[k * 2 + c] = s;
    if (t < 2) {
        float sb = 0.f;
        for (int j = 0; j < 128; j++) sb += mpb1[j] * mpW2[j * 2 + t];
        g_bc[t] = sb + mpb2[t];
    }
}

// ---------------- launch ----------------
extern "C" void kernel_launch(void* const* d_in, const int* in_sizes, int n_in,
                              void* d_out, int out_size) {
    const float* x    = (const float*)d_in[0];
    const int*   ei   = (const int*)d_in[1];
    const int*   srcI = ei;
    const int*   dstI = ei + NE;
    const float* W1 = (const float*)d_in[2];
    const float* b1 = (const float*)d_in[3];
    const float* W2 = (const float*)d_in[4];
    const float* b2 = (const float*)d_in[5];
    const float* W3 = (const float*)d_in[6];
    const float* b3 = (const float*)d_in[7];
    const float* ln1g = (const float*)d_in[8];
    const float* ln1b = (const float*)d_in[9];
    const float* ln2g = (const float*)d_in[10];
    const float* ln2b = (const float*)d_in[11];
    const float* mpW1 = (const float*)d_in[12];
    const float* mpb1 = (const float*)d_in[13];
    const float* mpW2 = (const float*)d_in[14];
    const float* mpb2 = (const float*)d_in[15];

    float* out  = (float*)d_out;
    float* emb  = out;
    float* logp = out + (size_t)NN * HD;

    float *bufA, *bufB;
    cudaGetSymbolAddress((void**)&bufA, g_bufA);
    cudaGetSymbolAddress((void**)&bufB, g_bufB);
    uint2 *bH, *bL;
    cudaGetSymbolAddress((void**)&bH, g_bH);
    cudaGetSymbolAddress((void**)&bL, g_bL);

    int smemSz = 128 * SMA_STRIDE * 4;
    cudaFuncSetAttribute(gemm_tc, cudaFuncAttributeMaxDynamicSharedMemorySize, smemSz);

    // graph preprocessing
    k_zero<<<(NN + 255) / 256, 256>>>();
    k_count<<<(NE + 255) / 256, 256>>>(dstI);
    k_scan<<<1, 1024>>>();
    k_scatter<<<(NE + 255) / 256, 256>>>(srcI, dstI);
    k_compose<<<1, 256>>>(mpW1, mpW2, mpb1, mpb2);
    k_bfrag<<<16, 256>>>(W1, 0);
    k_bfrag<<<16, 256>>>(W2, 1);
    k_bfrag<<<16, 256>>>(W3, 2);

    int gemmBlocks = (NN + 127) / 128;
    int aggBlocks = (NN * 32 + 255) / 256;

    // layer 0
    gemm_tc<<<gemmBlocks, 256, smemSz>>>(x, bH, bL, bufA, NN);
    k_agg<<<aggBlocks, 256>>>(bufA, b1, ln1g, ln1b, bufB, 1, nullptr);
    // layer 1
    gemm_tc<<<gemmBlocks, 256, smemSz>>>(bufB, bH + 4096, bL + 4096, bufA, NN);
    k_agg<<<aggBlocks, 256>>>(bufA, b2, ln2g, ln2b, bufB, 1, nullptr);
    // layer 2 -> emb + fused head
    gemm_tc<<<gemmBlocks, 256, smemSz>>>(bufB, bH + 8192, bL + 8192, bufA, NN);
    k_agg<<<aggBlocks, 256>>>(bufA, b3, nullptr, nullptr, emb, 0, logp);
}

// round 15
// speedup vs baseline: 1.4584x; 1.0310x over previous
#include <cuda_runtime.h>
#include <cuda_bf16.h>
#include <math.h>
#include <stdint.h>

#define NN 100000
#define NE 1600000
#define HD 128
#define EPSV 1e-5f
#define AROW 68   // uint32 stride per row (64 pairs + 4 pad)

// ---------------- scratch ----------------
__device__ int   g_deg[NN];
__device__ int   g_fill[NN];
__device__ int   g_off[NN + 1];
__device__ float g_dinv[NN];
__device__ int   g_csrc[NE];
__device__ float g_bufA[(size_t)NN * HD];
__device__ float g_bufB[(size_t)NN * HD];
__device__ float g_Wc[HD * 2];
__device__ float g_bc[2];
// B fragments (hi/lo bf16x2 pairs), order: [mat 3][ntile 16][k 8][lane 32]
__device__ uint2 g_bH[3][4096];
__device__ uint2 g_bL[3][4096];

// ---------------- graph preprocessing ----------------
__global__ void k_zero() {
    int i = blockIdx.x * blockDim.x + threadIdx.x;
    if (i < NN) { g_deg[i] = 0; g_fill[i] = 0; }
}

__global__ void k_count(const int* __restrict__ dst) {
    int i = blockIdx.x * blockDim.x + threadIdx.x;
    if (i < NE) atomicAdd(&g_deg[dst[i]], 1);
}

__global__ void k_scan() {
    __shared__ int ss[1024];
    const int T = 1024;
    const int CH = (NN + T - 1) / T;
    int t = threadIdx.x;
    int lo = t * CH; if (lo > NN) lo = NN;
    int hi = lo + CH; if (hi > NN) hi = NN;
    int s = 0;
    for (int i = lo; i < hi; i++) s += g_deg[i];
    ss[t] = s;
    __syncthreads();
    for (int d = 1; d < T; d <<= 1) {
        int v = (t >= d) ? ss[t - d] : 0;
        __syncthreads();
        ss[t] += v;
        __syncthreads();
    }
    int run = (t == 0) ? 0 : ss[t - 1];
    for (int i = lo; i < hi; i++) {
        g_off[i] = run;
        int dg = g_deg[i];
        run += dg;
        g_dinv[i] = rsqrtf((float)(dg + 1));
    }
    if (t == T - 1) g_off[NN] = run;
}

__global__ void k_scatter(const int* __restrict__ src, const int* __restrict__ dst) {
    int i = blockIdx.x * blockDim.x + threadIdx.x;
    if (i < NE) {
        int d = dst[i];
        int p = g_off[d] + atomicAdd(&g_fill[d], 1);
        g_csrc[p] = src[i];
    }
}

// ---------------- bf16 split helpers ----------------
__device__ __forceinline__ uint32_t pack_bf16_hi(float a, float b) {
    __nv_bfloat162 p = __floats2bfloat162_rn(a, b);
    return *(uint32_t*)&p;
}
__device__ __forceinline__ float bf16_resid(float x) {
    return x - __bfloat162float(__float2bfloat16_rn(x));
}
__device__ __forceinline__ void mma_bf16(float* d, const uint32_t* a, uint32_t b0, uint32_t b1) {
    asm volatile(
        "mma.sync.aligned.m16n8k16.row.col.f32.bf16.bf16.f32 "
        "{%0,%1,%2,%3}, {%4,%5,%6,%7}, {%8,%9}, {%0,%1,%2,%3};"
        : "+f"(d[0]), "+f"(d[1]), "+f"(d[2]), "+f"(d[3])
        : "r"(a[0]), "r"(a[1]), "r"(a[2]), "r"(a[3]), "r"(b0), "r"(b1));
}

// precompute B fragments for all 3 matrices in one launch
__global__ void k_bfrag_all(const float* __restrict__ W1, const float* __restrict__ W2,
                            const float* __restrict__ W3) {
    int sg = blockIdx.x * blockDim.x + threadIdx.x;   // 0..12287
    if (sg >= 3 * 4096) return;
    int mat = sg >> 12;
    int s = sg & 4095;
    const float* W = (mat == 0) ? W1 : (mat == 1) ? W2 : W3;
    int ti = s >> 8;
    int k  = (s >> 5) & 7;
    int ln = s & 31;
    int g = ln >> 2, tt = ln & 3;
    int c = ti * 8 + g;
    int r0 = k * 16 + 2 * tt;
    int r1 = k * 16 + 2 * tt + 8;
    float v00 = W[r0 * 128 + c],       v01 = W[(r0 + 1) * 128 + c];
    float v10 = W[r1 * 128 + c],       v11 = W[(r1 + 1) * 128 + c];
    g_bH[mat][s] = make_uint2(pack_bf16_hi(v00, v01), pack_bf16_hi(v10, v11));
    g_bL[mat][s] = make_uint2(pack_bf16_hi(bf16_resid(v00), bf16_resid(v01)),
                              pack_bf16_hi(bf16_resid(v10), bf16_resid(v11)));
}

// ---------------- tensor-core bf16 (3-term split) GEMM ----------------
// smem: aHi[128][AROW] + aLo[128][AROW] uint32 = 69632 B; 2 CTA/SM
__global__ __launch_bounds__(256, 2) void gemm_tc(const float* __restrict__ A,
                                                  const uint2* __restrict__ bh,
                                                  const uint2* __restrict__ bl,
                                                  float* __restrict__ C, int M) {
    extern __shared__ uint32_t smU[];
    uint32_t* aHi = smU;                   // [128][AROW]
    uint32_t* aLo = smU + 128 * AROW;      // [128][AROW]
    int tid = threadIdx.x;
    int bm = blockIdx.x * 128;

    // staging: load float4 rows coalesced, convert ONCE to bf16x2 hi/lo pairs
    for (int s = tid; s < 128 * 32; s += 256) {
        int row = s >> 5, q = s & 31;          // q-th float4 of the row
        int gr = bm + row;
        float4 v = (gr < M) ? *(const float4*)(A + (size_t)gr * 128 + q * 4)
                            : make_float4(0.f, 0.f, 0.f, 0.f);
        uint2 hi = make_uint2(pack_bf16_hi(v.x, v.y), pack_bf16_hi(v.z, v.w));
        uint2 lo = make_uint2(pack_bf16_hi(bf16_resid(v.x), bf16_resid(v.y)),
                              pack_bf16_hi(bf16_resid(v.z), bf16_resid(v.w)));
        *(uint2*)&aHi[row * AROW + q * 2] = hi;   // 8B aligned (AROW even)
        *(uint2*)&aLo[row * AROW + q * 2] = lo;
    }
    __syncthreads();

    int wid = tid >> 5, ln = tid & 31;
    int wm = wid & 3;    // m-tiles wm*2, wm*2+1
    int wn = wid >> 2;   // n-tiles wn*8 .. +7
    int g = ln >> 2, tt = ln & 3;

    float acc[2][8][4] = {};

#pragma unroll
    for (int k = 0; k < 8; k++) {        // k-chunks of 16
        uint32_t ah[2][4], al[2][4];
#pragma unroll
        for (int mi = 0; mi < 2; mi++) {
            int row0 = (wm * 2 + mi) * 16 + g;
            int base0 = row0 * AROW + k * 8 + tt;
            int base1 = (row0 + 8) * AROW + k * 8 + tt;
            ah[mi][0] = aHi[base0];
            ah[mi][1] = aHi[base1];
            ah[mi][2] = aHi[base0 + 4];
            ah[mi][3] = aHi[base1 + 4];
            al[mi][0] = aLo[base0];
            al[mi][1] = aLo[base1];
            al[mi][2] = aLo[base0 + 4];
            al[mi][3] = aLo[base1 + 4];
        }
#pragma unroll
        for (int ti = 0; ti < 8; ti++) {
            int idx = ((wn * 8 + ti) * 8 + k) * 32 + ln;
            uint2 H = bh[idx];
            uint2 L = bl[idx];
#pragma unroll
            for (int mi = 0; mi < 2; mi++) {
                mma_bf16(acc[mi][ti], ah[mi], H.x, H.y);   // ah*bh
                mma_bf16(acc[mi][ti], al[mi], H.x, H.y);   // al*bh
                mma_bf16(acc[mi][ti], ah[mi], L.x, L.y);   // ah*bl
            }
        }
    }

    // epilogue
#pragma unroll
    for (int mi = 0; mi < 2; mi++) {
        int row0 = bm + (wm * 2 + mi) * 16 + g;
        int row1 = row0 + 8;
#pragma unroll
        for (int ti = 0; ti < 8; ti++) {
            int col = (wn * 8 + ti) * 8 + tt * 2;
            if (row0 < M)
                *(float2*)(C + (size_t)row0 * 128 + col) = make_float2(acc[mi][ti][0], acc[mi][ti][1]);
            if (row1 < M)
                *(float2*)(C + (size_t)row1 * 128 + col) = make_float2(acc[mi][ti][2], acc[mi][ti][3]);
        }
    }
}

// ---------------- aggregation (+bias [+relu+LN | head]) ; warp per node ----------------
__global__ void k_agg(const float* __restrict__ lin, const float* __restrict__ bias,
                      const float* __restrict__ lng, const float* __restrict__ lnb,
                      float* __restrict__ outp, int doLN, float* __restrict__ logp) {
    int gtid = blockIdx.x * blockDim.x + threadIdx.x;
    int node = gtid >> 5;
    if (node >= NN) return;
    int lane = gtid & 31;

    float dn = g_dinv[node];
    const float4* rowp = (const float4*)(lin + (size_t)node * HD);
    float4 v = rowp[lane];
    float w0 = dn * dn;
    float4 acc = make_float4(v.x * w0, v.y * w0, v.z * w0, v.w * w0);

    int e0 = g_off[node], e1 = g_off[node + 1];
    int e = e0;
    for (; e + 8 <= e1; e += 8) {
        int s0 = g_csrc[e + 0];
        int s1 = g_csrc[e + 1];
        int s2 = g_csrc[e + 2];
        int s3 = g_csrc[e + 3];
        int s4 = g_csrc[e + 4];
        int s5 = g_csrc[e + 5];
        int s6 = g_csrc[e + 6];
        int s7 = g_csrc[e + 7];
        float w_0 = g_dinv[s0] * dn;
        float w_1 = g_dinv[s1] * dn;
        float w_2 = g_dinv[s2] * dn;
        float w_3 = g_dinv[s3] * dn;
        float w_4 = g_dinv[s4] * dn;
        float w_5 = g_dinv[s5] * dn;
        float w_6 = g_dinv[s6] * dn;
        float w_7 = g_dinv[s7] * dn;
        float4 u0 = ((const float4*)(lin + (size_t)s0 * HD))[lane];
        float4 u1 = ((const float4*)(lin + (size_t)s1 * HD))[lane];
        float4 u2 = ((const float4*)(lin + (size_t)s2 * HD))[lane];
        float4 u3 = ((const float4*)(lin + (size_t)s3 * HD))[lane];
        float4 u4 = ((const float4*)(lin + (size_t)s4 * HD))[lane];
        float4 u5 = ((const float4*)(lin + (size_t)s5 * HD))[lane];
        float4 u6 = ((const float4*)(lin + (size_t)s6 * HD))[lane];
        float4 u7 = ((const float4*)(lin + (size_t)s7 * HD))[lane];
        acc.x += u0.x * w_0; acc.y += u0.y * w_0; acc.z += u0.z * w_0; acc.w += u0.w * w_0;
        acc.x += u1.x * w_1; acc.y += u1.y * w_1; acc.z += u1.z * w_1; acc.w += u1.w * w_1;
        acc.x += u2.x * w_2; acc.y += u2.y * w_2; acc.z += u2.z * w_2; acc.w += u2.w * w_2;
        acc.x += u3.x * w_3; acc.y += u3.y * w_3; acc.z += u3.z * w_3; acc.w += u3.w * w_3;
        acc.x += u4.x * w_4; acc.y += u4.y * w_4; acc.z += u4.z * w_4; acc.w += u4.w * w_4;
        acc.x += u5.x * w_5; acc.y += u5.y * w_5; acc.z += u5.z * w_5; acc.w += u5.w * w_5;
        acc.x += u6.x * w_6; acc.y += u6.y * w_6; acc.z += u6.z * w_6; acc.w += u6.w * w_6;
        acc.x += u7.x * w_7; acc.y += u7.y * w_7; acc.z += u7.z * w_7; acc.w += u7.w * w_7;
    }
    for (; e < e1; e++) {
        int s = g_csrc[e];
        float w = g_dinv[s] * dn;
        float4 u = ((const float4*)(lin + (size_t)s * HD))[lane];
        acc.x += u.x * w; acc.y += u.y * w; acc.z += u.z * w; acc.w += u.w * w;
    }
    float4 bb = ((const float4*)bias)[lane];
    acc.x += bb.x; acc.y += bb.y; acc.z += bb.z; acc.w += bb.w;

    if (doLN) {
        acc.x = fmaxf(acc.x, 0.f); acc.y = fmaxf(acc.y, 0.f);
        acc.z = fmaxf(acc.z, 0.f); acc.w = fmaxf(acc.w, 0.f);
        float s1 = acc.x + acc.y + acc.z + acc.w;
        float s2 = acc.x * acc.x + acc.y * acc.y + acc.z * acc.z + acc.w * acc.w;
#pragma unroll
        for (int o = 16; o > 0; o >>= 1) {
            s1 += __shfl_xor_sync(0xffffffffu, s1, o);
            s2 += __shfl_xor_sync(0xffffffffu, s2, o);
        }
        float mu = s1 * (1.0f / HD);
        float var = s2 * (1.0f / HD) - mu * mu;
        float r = rsqrtf(var + EPSV);
        float4 gg = ((const float4*)lng)[lane];
        float4 bl = ((const float4*)lnb)[lane];
        acc.x = (acc.x - mu) * r * gg.x + bl.x;
        acc.y = (acc.y - mu) * r * gg.y + bl.y;
        acc.z = (acc.z - mu) * r * gg.z + bl.z;
        acc.w = (acc.w - mu) * r * gg.w + bl.w;
        ((float4*)(outp + (size_t)node * HD))[lane] = acc;
    } else {
        ((float4*)(outp + (size_t)node * HD))[lane] = acc;
        float4 r = make_float4(fmaxf(acc.x, 0.f), fmaxf(acc.y, 0.f),
                               fmaxf(acc.z, 0.f), fmaxf(acc.w, 0.f));
        const float4* wp = (const float4*)g_Wc;
        float4 wa = wp[lane * 2];
        float4 wb = wp[lane * 2 + 1];
        float l0 = r.x * wa.x + r.y * wa.z + r.z * wb.x + r.w * wb.z;
        float l1 = r.x * wa.y + r.y * wa.w + r.z * wb.y + r.w * wb.w;
#pragma unroll
        for (int o = 16; o > 0; o >>= 1) {
            l0 += __shfl_xor_sync(0xffffffffu, l0, o);
            l1 += __shfl_xor_sync(0xffffffffu, l1, o);
        }
        if (lane == 0) {
            l0 += g_bc[0]; l1 += g_bc[1];
            float m = fmaxf(l0, l1);
            float lse = m + logf(expf(l0 - m) + expf(l1 - m));
            logp[(size_t)node * 2 + 0] = l0 - lse;
            logp[(size_t)node * 2 + 1] = l1 - lse;
        }
    }
}

// ---------------- MLP head collapse ----------------
__global__ void k_compose(const float* __restrict__ mpW1, const float* __restrict__ mpW2,
                          const float* __restrict__ mpb1, const float* __restrict__ mpb2) {
    int t = threadIdx.x;
    int k = t >> 1, c = t & 1;
    float s = 0.f;
    for (int j = 0; j < 128; j++) s += mpW1[k * 128 + j] * mpW2[j * 2 + c];
    g_Wc[k * 2 + c] = s;
    if (t < 2) {
        float sb = 0.f;
        for (int j = 0; j < 128; j++) sb += mpb1[j] * mpW2[j * 2 + t];
        g_bc[t] = sb + mpb2[t];
    }
}

// ---------------- launch ----------------
extern "C" void kernel_launch(void* const* d_in, const int* in_sizes, int n_in,
                              void* d_out, int out_size) {
    const float* x    = (const float*)d_in[0];
    const int*   ei   = (const int*)d_in[1];
    const int*   srcI = ei;
    const int*   dstI = ei + NE;
    const float* W1 = (const float*)d_in[2];
    const float* b1 = (const float*)d_in[3];
    const float* W2 = (const float*)d_in[4];
    const float* b2 = (const float*)d_in[5];
    const float* W3 = (const float*)d_in[6];
    const float* b3 = (const float*)d_in[7];
    const float* ln1g = (const float*)d_in[8];
    const float* ln1b = (const float*)d_in[9];
    const float* ln2g = (const float*)d_in[10];
    const float* ln2b = (const float*)d_in[11];
    const float* mpW1 = (const float*)d_in[12];
    const float* mpb1 = (const float*)d_in[13];
    const float* mpW2 = (const float*)d_in[14];
    const float* mpb2 = (const float*)d_in[15];

    float* out  = (float*)d_out;
    float* emb  = out;
    float* logp = out + (size_t)NN * HD;

    float *bufA, *bufB;
    cudaGetSymbolAddress((void**)&bufA, g_bufA);
    cudaGetSymbolAddress((void**)&bufB, g_bufB);
    uint2 *bH, *bL;
    cudaGetSymbolAddress((void**)&bH, g_bH);
    cudaGetSymbolAddress((void**)&bL, g_bL);

    int smemSz = 2 * 128 * AROW * 4;   // 69632 B
    cudaFuncSetAttribute(gemm_tc, cudaFuncAttributeMaxDynamicSharedMemorySize, smemSz);

    // graph preprocessing
    k_zero<<<(NN + 255) / 256, 256>>>();
    k_count<<<(NE + 255) / 256, 256>>>(dstI);
    k_scan<<<1, 1024>>>();
    k_scatter<<<(NE + 255) / 256, 256>>>(srcI, dstI);
    k_compose<<<1, 256>>>(mpW1, mpW2, mpb1, mpb2);
    k_bfrag_all<<<48, 256>>>(W1, W2, W3);

    int gemmBlocks = (NN + 127) / 128;
    int aggBlocks = (NN * 32 + 255) / 256;

    // layer 0
    gemm_tc<<<gemmBlocks, 256, smemSz>>>(x, bH, bL, bufA, NN);
    k_agg<<<aggBlocks, 256>>>(bufA, b1, ln1g, ln1b, bufB, 1, nullptr);
    // layer 1
    gemm_tc<<<gemmBlocks, 256, smemSz>>>(bufB, bH + 4096, bL + 4096, bufA, NN);
    k_agg<<<aggBlocks, 256>>>(bufA, b2, ln2g, ln2b, bufB, 1, nullptr);
    // layer 2 -> emb + fused head
    gemm_tc<<<gemmBlocks, 256, smemSz>>>(bufB, bH + 8192, bL + 8192, bufA, NN);
    k_agg<<<aggBlocks, 256>>>(bufA, b3, nullptr, nullptr, emb, 0, logp);
}

// round 16
// speedup vs baseline: 1.7647x; 1.2100x over previous
#include <cuda_runtime.h>
#include <cuda_bf16.h>
#include <cuda_fp16.h>
#include <math.h>
#include <stdint.h>

#define NN 100000
#define NE 1600000
#define HD 128
#define EPSV 1e-5f
#define AROW 68   // uint32 stride per row (64 pairs + 4 pad)

// ---------------- scratch ----------------
__device__ int   g_deg[NN];
__device__ int   g_fill[NN];
__device__ int   g_off[NN + 1];
__device__ float g_dinv[NN];
__device__ int   g_csrc[NE];
__device__ float g_bufA[(size_t)NN * HD];          // fp32 gemm input (agg output)
__device__ uint32_t g_h16[(size_t)NN * 64];        // fp16x2 prescaled gemm output (agg gather src)
__device__ float g_Wc[HD * 2];
__device__ float g_bc[2];
// B fragments (hi/lo bf16x2 pairs), order: [mat 3][ntile 16][k 8][lane 32]
__device__ uint2 g_bH[3][4096];
__device__ uint2 g_bL[3][4096];

// ---------------- graph preprocessing ----------------
__global__ void k_zero() {
    int i = blockIdx.x * blockDim.x + threadIdx.x;
    if (i < NN) { g_deg[i] = 0; g_fill[i] = 0; }
}

__global__ void k_count(const int* __restrict__ dst) {
    int i = blockIdx.x * blockDim.x + threadIdx.x;
    if (i < NE) atomicAdd(&g_deg[dst[i]], 1);
}

__global__ void k_scan() {
    __shared__ int ss[1024];
    const int T = 1024;
    const int CH = (NN + T - 1) / T;
    int t = threadIdx.x;
    int lo = t * CH; if (lo > NN) lo = NN;
    int hi = lo + CH; if (hi > NN) hi = NN;
    int s = 0;
    for (int i = lo; i < hi; i++) s += g_deg[i];
    ss[t] = s;
    __syncthreads();
    for (int d = 1; d < T; d <<= 1) {
        int v = (t >= d) ? ss[t - d] : 0;
        __syncthreads();
        ss[t] += v;
        __syncthreads();
    }
    int run = (t == 0) ? 0 : ss[t - 1];
    for (int i = lo; i < hi; i++) {
        g_off[i] = run;
        int dg = g_deg[i];
        run += dg;
        g_dinv[i] = rsqrtf((float)(dg + 1));
    }
    if (t == T - 1) g_off[NN] = run;
}

__global__ void k_scatter(const int* __restrict__ src, const int* __restrict__ dst) {
    int i = blockIdx.x * blockDim.x + threadIdx.x;
    if (i < NE) {
        int d = dst[i];
        int p = g_off[d] + atomicAdd(&g_fill[d], 1);
        g_csrc[p] = src[i];
    }
}

// ---------------- bf16 split helpers ----------------
__device__ __forceinline__ uint32_t pack_bf16_hi(float a, float b) {
    __nv_bfloat162 p = __floats2bfloat162_rn(a, b);
    return *(uint32_t*)&p;
}
__device__ __forceinline__ float bf16_resid(float x) {
    return x - __bfloat162float(__float2bfloat16_rn(x));
}
__device__ __forceinline__ void mma_bf16(float* d, const uint32_t* a, uint32_t b0, uint32_t b1) {
    asm volatile(
        "mma.sync.aligned.m16n8k16.row.col.f32.bf16.bf16.f32 "
        "{%0,%1,%2,%3}, {%4,%5,%6,%7}, {%8,%9}, {%0,%1,%2,%3};"
        : "+f"(d[0]), "+f"(d[1]), "+f"(d[2]), "+f"(d[3])
        : "r"(a[0]), "r"(a[1]), "r"(a[2]), "r"(a[3]), "r"(b0), "r"(b1));
}
__device__ __forceinline__ float2 h2f(uint32_t u) {
    __half2 h = *(__half2*)&u;
    return __half22float2(h);
}

// precompute B fragments for all 3 matrices in one launch
__global__ void k_bfrag_all(const float* __restrict__ W1, const float* __restrict__ W2,
                            const float* __restrict__ W3) {
    int sg = blockIdx.x * blockDim.x + threadIdx.x;
    if (sg >= 3 * 4096) return;
    int mat = sg >> 12;
    int s = sg & 4095;
    const float* W = (mat == 0) ? W1 : (mat == 1) ? W2 : W3;
    int ti = s >> 8;
    int k  = (s >> 5) & 7;
    int ln = s & 31;
    int g = ln >> 2, tt = ln & 3;
    int c = ti * 8 + g;
    int r0 = k * 16 + 2 * tt;
    int r1 = k * 16 + 2 * tt + 8;
    float v00 = W[r0 * 128 + c],       v01 = W[(r0 + 1) * 128 + c];
    float v10 = W[r1 * 128 + c],       v11 = W[(r1 + 1) * 128 + c];
    g_bH[mat][s] = make_uint2(pack_bf16_hi(v00, v01), pack_bf16_hi(v10, v11));
    g_bL[mat][s] = make_uint2(pack_bf16_hi(bf16_resid(v00), bf16_resid(v01)),
                              pack_bf16_hi(bf16_resid(v10), bf16_resid(v11)));
}

// ---------------- tensor-core bf16 (3-term split) GEMM ----------------
// out: prescaled fp16x2 (row r multiplied by g_dinv[r])
__global__ __launch_bounds__(256, 2) void gemm_tc(const float* __restrict__ A,
                                                  const uint2* __restrict__ bh,
                                                  const uint2* __restrict__ bl,
                                                  uint32_t* __restrict__ C16, int M) {
    extern __shared__ uint32_t smU[];
    uint32_t* aHi = smU;                   // [128][AROW]
    uint32_t* aLo = smU + 128 * AROW;      // [128][AROW]
    int tid = threadIdx.x;
    int bm = blockIdx.x * 128;

    // staging: load float4 rows coalesced, convert ONCE to bf16x2 hi/lo pairs
    for (int s = tid; s < 128 * 32; s += 256) {
        int row = s >> 5, q = s & 31;
        int gr = bm + row;
        float4 v = (gr < M) ? *(const float4*)(A + (size_t)gr * 128 + q * 4)
                            : make_float4(0.f, 0.f, 0.f, 0.f);
        uint2 hi = make_uint2(pack_bf16_hi(v.x, v.y), pack_bf16_hi(v.z, v.w));
        uint2 lo = make_uint2(pack_bf16_hi(bf16_resid(v.x), bf16_resid(v.y)),
                              pack_bf16_hi(bf16_resid(v.z), bf16_resid(v.w)));
        *(uint2*)&aHi[row * AROW + q * 2] = hi;
        *(uint2*)&aLo[row * AROW + q * 2] = lo;
    }
    __syncthreads();

    int wid = tid >> 5, ln = tid & 31;
    int wm = wid & 3;
    int wn = wid >> 2;
    int g = ln >> 2, tt = ln & 3;

    float acc[2][8][4] = {};

#pragma unroll
    for (int k = 0; k < 8; k++) {
        uint32_t ah[2][4], al[2][4];
#pragma unroll
        for (int mi = 0; mi < 2; mi++) {
            int row0 = (wm * 2 + mi) * 16 + g;
            int base0 = row0 * AROW + k * 8 + tt;
            int base1 = (row0 + 8) * AROW + k * 8 + tt;
            ah[mi][0] = aHi[base0];
            ah[mi][1] = aHi[base1];
            ah[mi][2] = aHi[base0 + 4];
            ah[mi][3] = aHi[base1 + 4];
            al[mi][0] = aLo[base0];
            al[mi][1] = aLo[base1];
            al[mi][2] = aLo[base0 + 4];
            al[mi][3] = aLo[base1 + 4];
        }
#pragma unroll
        for (int ti = 0; ti < 8; ti++) {
            int idx = ((wn * 8 + ti) * 8 + k) * 32 + ln;
            uint2 H = bh[idx];
            uint2 L = bl[idx];
#pragma unroll
            for (int mi = 0; mi < 2; mi++) {
                mma_bf16(acc[mi][ti], ah[mi], H.x, H.y);
                mma_bf16(acc[mi][ti], al[mi], H.x, H.y);
                mma_bf16(acc[mi][ti], ah[mi], L.x, L.y);
            }
        }
    }

    // epilogue: prescale by dinv[row], store fp16x2
#pragma unroll
    for (int mi = 0; mi < 2; mi++) {
        int row0 = bm + (wm * 2 + mi) * 16 + g;
        int row1 = row0 + 8;
        float w0 = (row0 < M) ? g_dinv[row0] : 0.f;
        float w1 = (row1 < M) ? g_dinv[row1] : 0.f;
#pragma unroll
        for (int ti = 0; ti < 8; ti++) {
            int cidx = (wn * 8 + ti) * 4 + tt;
            if (row0 < M) {
                __half2 h = __floats2half2_rn(acc[mi][ti][0] * w0, acc[mi][ti][1] * w0);
                C16[(size_t)row0 * 64 + cidx] = *(uint32_t*)&h;
            }
            if (row1 < M) {
                __half2 h = __floats2half2_rn(acc[mi][ti][2] * w1, acc[mi][ti][3] * w1);
                C16[(size_t)row1 * 64 + cidx] = *(uint32_t*)&h;
            }
        }
    }
}

// ---------------- aggregation: pure fp16 row sum, then *dinv +bias [+relu+LN | head] ----
__global__ void k_agg(const uint32_t* __restrict__ lin16, const float* __restrict__ bias,
                      const float* __restrict__ lng, const float* __restrict__ lnb,
                      float* __restrict__ outp, int doLN, float* __restrict__ logp) {
    int gtid = blockIdx.x * blockDim.x + threadIdx.x;
    int node = gtid >> 5;
    if (node >= NN) return;
    int lane = gtid & 31;

    float dn = g_dinv[node];
    // self (already prescaled by dinv[node])
    uint2 su = *(const uint2*)(lin16 + (size_t)node * 64 + lane * 2);
    float2 s0 = h2f(su.x), s1 = h2f(su.y);
    float4 acc = make_float4(s0.x, s0.y, s1.x, s1.y);

    int e0 = g_off[node], e1 = g_off[node + 1];
    int e = e0;
    for (; e + 8 <= e1; e += 8) {
        int i0 = g_csrc[e + 0];
        int i1 = g_csrc[e + 1];
        int i2 = g_csrc[e + 2];
        int i3 = g_csrc[e + 3];
        int i4 = g_csrc[e + 4];
        int i5 = g_csrc[e + 5];
        int i6 = g_csrc[e + 6];
        int i7 = g_csrc[e + 7];
        uint2 u0 = *(const uint2*)(lin16 + (size_t)i0 * 64 + lane * 2);
        uint2 u1 = *(const uint2*)(lin16 + (size_t)i1 * 64 + lane * 2);
        uint2 u2 = *(const uint2*)(lin16 + (size_t)i2 * 64 + lane * 2);
        uint2 u3 = *(const uint2*)(lin16 + (size_t)i3 * 64 + lane * 2);
        uint2 u4 = *(const uint2*)(lin16 + (size_t)i4 * 64 + lane * 2);
        uint2 u5 = *(const uint2*)(lin16 + (size_t)i5 * 64 + lane * 2);
        uint2 u6 = *(const uint2*)(lin16 + (size_t)i6 * 64 + lane * 2);
        uint2 u7 = *(const uint2*)(lin16 + (size_t)i7 * 64 + lane * 2);
        float2 a0, a1;
        a0 = h2f(u0.x); a1 = h2f(u0.y); acc.x += a0.x; acc.y += a0.y; acc.z += a1.x; acc.w += a1.y;
        a0 = h2f(u1.x); a1 = h2f(u1.y); acc.x += a0.x; acc.y += a0.y; acc.z += a1.x; acc.w += a1.y;
        a0 = h2f(u2.x); a1 = h2f(u2.y); acc.x += a0.x; acc.y += a0.y; acc.z += a1.x; acc.w += a1.y;
        a0 = h2f(u3.x); a1 = h2f(u3.y); acc.x += a0.x; acc.y += a0.y; acc.z += a1.x; acc.w += a1.y;
        a0 = h2f(u4.x); a1 = h2f(u4.y); acc.x += a0.x; acc.y += a0.y; acc.z += a1.x; acc.w += a1.y;
        a0 = h2f(u5.x); a1 = h2f(u5.y); acc.x += a0.x; acc.y += a0.y; acc.z += a1.x; acc.w += a1.y;
        a0 = h2f(u6.x); a1 = h2f(u6.y); acc.x += a0.x; acc.y += a0.y; acc.z += a1.x; acc.w += a1.y;
        a0 = h2f(u7.x); a1 = h2f(u7.y); acc.x += a0.x; acc.y += a0.y; acc.z += a1.x; acc.w += a1.y;
    }
    for (; e < e1; e++) {
        int s = g_csrc[e];
        uint2 u = *(const uint2*)(lin16 + (size_t)s * 64 + lane * 2);
        float2 a0 = h2f(u.x), a1 = h2f(u.y);
        acc.x += a0.x; acc.y += a0.y; acc.z += a1.x; acc.w += a1.y;
    }
    // final scale by dinv[dst] + bias
    float4 bb = ((const float4*)bias)[lane];
    acc.x = acc.x * dn + bb.x;
    acc.y = acc.y * dn + bb.y;
    acc.z = acc.z * dn + bb.z;
    acc.w = acc.w * dn + bb.w;

    if (doLN) {
        acc.x = fmaxf(acc.x, 0.f); acc.y = fmaxf(acc.y, 0.f);
        acc.z = fmaxf(acc.z, 0.f); acc.w = fmaxf(acc.w, 0.f);
        float s1 = acc.x + acc.y + acc.z + acc.w;
        float s2 = acc.x * acc.x + acc.y * acc.y + acc.z * acc.z + acc.w * acc.w;
#pragma unroll
        for (int o = 16; o > 0; o >>= 1) {
            s1 += __shfl_xor_sync(0xffffffffu, s1, o);
            s2 += __shfl_xor_sync(0xffffffffu, s2, o);
        }
        float mu = s1 * (1.0f / HD);
        float var = s2 * (1.0f / HD) - mu * mu;
        float r = rsqrtf(var + EPSV);
        float4 gg = ((const float4*)lng)[lane];
        float4 bl = ((const float4*)lnb)[lane];
        acc.x = (acc.x - mu) * r * gg.x + bl.x;
        acc.y = (acc.y - mu) * r * gg.y + bl.y;
        acc.z = (acc.z - mu) * r * gg.z + bl.z;
        acc.w = (acc.w - mu) * r * gg.w + bl.w;
        ((float4*)(outp + (size_t)node * HD))[lane] = acc;
    } else {
        ((float4*)(outp + (size_t)node * HD))[lane] = acc;
        float4 r = make_float4(fmaxf(acc.x, 0.f), fmaxf(acc.y, 0.f),
                               fmaxf(acc.z, 0.f), fmaxf(acc.w, 0.f));
        const float4* wp = (const float4*)g_Wc;
        float4 wa = wp[lane * 2];
        float4 wb = wp[lane * 2 + 1];
        float l0 = r.x * wa.x + r.y * wa.z + r.z * wb.x + r.w * wb.z;
        float l1 = r.x * wa.y + r.y * wa.w + r.z * wb.y + r.w * wb.w;
#pragma unroll
        for (int o = 16; o > 0; o >>= 1) {
            l0 += __shfl_xor_sync(0xffffffffu, l0, o);
            l1 += __shfl_xor_sync(0xffffffffu, l1, o);
        }
        if (lane == 0) {
            l0 += g_bc[0]; l1 += g_bc[1];
            float m = fmaxf(l0, l1);
            float lse = m + logf(expf(l0 - m) + expf(l1 - m));
            logp[(size_t)node * 2 + 0] = l0 - lse;
            logp[(size_t)node * 2 + 1] = l1 - lse;
        }
    }
}

// ---------------- MLP head collapse ----------------
__global__ void k_compose(const float* __restrict__ mpW1, const float* __restrict__ mpW2,
                          const float* __restrict__ mpb1, const float* __restrict__ mpb2) {
    int t = threadIdx.x;
    int k = t >> 1, c = t & 1;
    float s = 0.f;
    for (int j = 0; j < 128; j++) s += mpW1[k * 128 + j] * mpW2[j * 2 + c];
    g_Wc[k * 2 + c] = s;
    if (t < 2) {
        float sb = 0.f;
        for (int j = 0; j < 128; j++) sb += mpb1[j] * mpW2[j * 2 + t];
        g_bc[t] = sb + mpb2[t];
    }
}

// ---------------- launch ----------------
extern "C" void kernel_launch(void* const* d_in, const int* in_sizes, int n_in,
                              void* d_out, int out_size) {
    const float* x    = (const float*)d_in[0];
    const int*   ei   = (const int*)d_in[1];
    const int*   srcI = ei;
    const int*   dstI = ei + NE;
    const float* W1 = (const float*)d_in[2];
    const float* b1 = (const float*)d_in[3];
    const float* W2 = (const float*)d_in[4];
    const float* b2 = (const float*)d_in[5];
    const float* W3 = (const float*)d_in[6];
    const float* b3 = (const float*)d_in[7];
    const float* ln1g = (const float*)d_in[8];
    const float* ln1b = (const float*)d_in[9];
    const float* ln2g = (const float*)d_in[10];
    const float* ln2b = (const float*)d_in[11];
    const float* mpW1 = (const float*)d_in[12];
    const float* mpb1 = (const float*)d_in[13];
    const float* mpW2 = (const float*)d_in[14];
    const float* mpb2 = (const float*)d_in[15];

    float* out  = (float*)d_out;
    float* emb  = out;
    float* logp = out + (size_t)NN * HD;

    float* bufA;
    uint32_t* h16;
    cudaGetSymbolAddress((void**)&bufA, g_bufA);
    cudaGetSymbolAddress((void**)&h16, g_h16);
    uint2 *bH, *bL;
    cudaGetSymbolAddress((void**)&bH, g_bH);
    cudaGetSymbolAddress((void**)&bL, g_bL);

    int smemSz = 2 * 128 * AROW * 4;   // 69632 B
    cudaFuncSetAttribute(gemm_tc, cudaFuncAttributeMaxDynamicSharedMemorySize, smemSz);

    // graph preprocessing (dinv must precede gemm epilogue)
    k_zero<<<(NN + 255) / 256, 256>>>();
    k_count<<<(NE + 255) / 256, 256>>>(dstI);
    k_scan<<<1, 1024>>>();
    k_scatter<<<(NE + 255) / 256, 256>>>(srcI, dstI);
    k_compose<<<1, 256>>>(mpW1, mpW2, mpb1, mpb2);
    k_bfrag_all<<<48, 256>>>(W1, W2, W3);

    int gemmBlocks = (NN + 127) / 128;
    int aggBlocks = (NN * 32 + 255) / 256;

    // layer 0
    gemm_tc<<<gemmBlocks, 256, smemSz>>>(x, bH, bL, h16, NN);
    k_agg<<<aggBlocks, 256>>>(h16, b1, ln1g, ln1b, bufA, 1, nullptr);
    // layer 1
    gemm_tc<<<gemmBlocks, 256, smemSz>>>(bufA, bH + 4096, bL + 4096, h16, NN);
    k_agg<<<aggBlocks, 256>>>(h16, b2, ln2g, ln2b, bufA, 1, nullptr);
    // layer 2 -> emb + fused head
    gemm_tc<<<gemmBlocks, 256, smemSz>>>(bufA, bH + 8192, bL + 8192, h16, NN);
    k_agg<<<aggBlocks, 256>>>(h16, b3, nullptr, nullptr, emb, 0, logp);
}